// round 1
// baseline (speedup 1.0000x reference)
#include <cuda_runtime.h>
#include <stdint.h>

#define NNODES 40000
#define NEDGES 640000
#define NGRAPH 64
#define DIN    128
#define DH     256
#define DOUTC  128

// ---- scratch (no allocations allowed) ----
__device__ float g_bufA[NNODES * DH];
__device__ float g_bufB[NNODES * DH];
__device__ float g_dis[NNODES];
__device__ float g_cnt[NGRAPH];

// ---------------------------------------------------------------------------
// small utility kernels
// ---------------------------------------------------------------------------
__global__ void fill_kernel(float4* __restrict__ p, float v, int n4) {
    int i = blockIdx.x * blockDim.x + threadIdx.x;
    float4 f = make_float4(v, v, v, v);
    for (; i < n4; i += gridDim.x * blockDim.x) p[i] = f;
}

__global__ void deg_kernel(const int* __restrict__ dst, int E) {
    int e = blockIdx.x * blockDim.x + threadIdx.x;
    if (e < E) atomicAdd(&g_dis[dst[e]], 1.0f);
}

__global__ void rsqrt_kernel(int n) {
    int i = blockIdx.x * blockDim.x + threadIdx.x;
    if (i < n) g_dis[i] = rsqrtf(g_dis[i]);
}

// ---------------------------------------------------------------------------
// fp32 tiled GEMM: C[N,M] = A[N,K] @ B[K,M]
// block (16,16), tile 64x64, K-tile 16, 4x4 per thread.
// Requires N%64==0, M%64==0, K%16==0 (true here: 40000=64*625, M in {256,128},
// K in {128,256}).
// ---------------------------------------------------------------------------
__global__ void gemm_kernel(const float* __restrict__ A, const float* __restrict__ B,
                            float* __restrict__ C, int K, int M) {
    __shared__ float As[16][64];
    __shared__ float Bs[16][64];
    const int tid = threadIdx.y * 16 + threadIdx.x;
    const int rowBase = blockIdx.y * 64;
    const int colBase = blockIdx.x * 64;

    float acc[4][4] = {};

    for (int k0 = 0; k0 < K; k0 += 16) {
        {   // A tile: 64 rows x 16 k, one float4 per thread, stored transposed
            int r  = tid >> 2;
            int kk = (tid & 3) * 4;
            float4 v = *(const float4*)(A + (size_t)(rowBase + r) * K + k0 + kk);
            As[kk + 0][r] = v.x; As[kk + 1][r] = v.y;
            As[kk + 2][r] = v.z; As[kk + 3][r] = v.w;
        }
        {   // B tile: 16 k x 64 cols
            int kr = tid >> 4;
            int cc = (tid & 15) * 4;
            float4 v = *(const float4*)(B + (size_t)(k0 + kr) * M + colBase + cc);
            Bs[kr][cc + 0] = v.x; Bs[kr][cc + 1] = v.y;
            Bs[kr][cc + 2] = v.z; Bs[kr][cc + 3] = v.w;
        }
        __syncthreads();
        #pragma unroll
        for (int kk = 0; kk < 16; ++kk) {
            float a[4], b[4];
            #pragma unroll
            for (int i = 0; i < 4; ++i) a[i] = As[kk][threadIdx.y * 4 + i];
            #pragma unroll
            for (int j = 0; j < 4; ++j) b[j] = Bs[kk][threadIdx.x * 4 + j];
            #pragma unroll
            for (int i = 0; i < 4; ++i)
                #pragma unroll
                for (int j = 0; j < 4; ++j) acc[i][j] += a[i] * b[j];
        }
        __syncthreads();
    }
    #pragma unroll
    for (int i = 0; i < 4; ++i) {
        int r = rowBase + threadIdx.y * 4 + i;
        float4 o = make_float4(acc[i][0], acc[i][1], acc[i][2], acc[i][3]);
        *(float4*)(C + (size_t)r * M + colBase + threadIdx.x * 4) = o;
    }
}

// ---------------------------------------------------------------------------
// edge scatter: one warp per edge, vector red.global.add.v4.f32
// agg[dst] += dis[src]*dis[dst] * h[src]
// ---------------------------------------------------------------------------
template <int H>
__global__ void scatter_kernel(const int* __restrict__ src, const int* __restrict__ dst,
                               const float* __restrict__ h, float* __restrict__ agg, int E) {
    int idx  = blockIdx.x * blockDim.x + threadIdx.x;
    int e    = idx >> 5;
    if (e >= E) return;
    int lane = idx & 31;
    int s = __ldg(&src[e]);
    int d = __ldg(&dst[e]);
    float coef = g_dis[s] * g_dis[d];
    const float4* hp = (const float4*)(h + (size_t)s * H) + lane;
    float4*       ap = (float4*)(agg + (size_t)d * H) + lane;
    #pragma unroll
    for (int i = 0; i < H / 128; ++i) {
        float4 v = __ldg(hp + i * 32);
        unsigned long long ga = __cvta_generic_to_global(ap + i * 32);
        asm volatile("red.global.add.v4.f32 [%0], {%1, %2, %3, %4};"
                     :: "l"(ga), "f"(v.x * coef), "f"(v.y * coef),
                        "f"(v.z * coef), "f"(v.w * coef)
                     : "memory");
    }
}

// ---------------------------------------------------------------------------
// finalize: out = agg + dis^2 * h + bias, optional relu (in place on agg)
// ---------------------------------------------------------------------------
template <bool RELU, int H>
__global__ void finalize_kernel(float* __restrict__ agg, const float* __restrict__ h,
                                const float* __restrict__ bias, int total) {
    int i = blockIdx.x * blockDim.x + threadIdx.x;
    if (i >= total) return;
    int n = i / H;
    int c = i - n * H;
    float dis = g_dis[n];
    float v = agg[i] + dis * dis * h[i] + __ldg(&bias[c]);
    agg[i] = RELU ? fmaxf(v, 0.0f) : v;
}

// ---------------------------------------------------------------------------
// pooling: batch is sorted, so accumulate in registers until graph id changes.
// block = 128 threads (one per channel), each block covers 256 nodes.
// ---------------------------------------------------------------------------
__global__ void pool_kernel(const float* __restrict__ ne, const int* __restrict__ batch,
                            float* __restrict__ gsum, int N) {
    int c  = threadIdx.x;  // 0..127
    int n0 = blockIdx.x * 256;
    int n1 = min(n0 + 256, N);
    float acc = 0.0f;
    int cur = -1;
    for (int n = n0; n < n1; ++n) {
        int g = __ldg(&batch[n]);
        if (g != cur) {
            if (cur >= 0) atomicAdd(&gsum[cur * DOUTC + c], acc);
            acc = 0.0f;
            cur = g;
        }
        acc += ne[(size_t)n * DOUTC + c];
    }
    if (cur >= 0) atomicAdd(&gsum[cur * DOUTC + c], acc);
}

__global__ void counts_kernel(const int* __restrict__ batch, int N) {
    __shared__ float s[NGRAPH];
    if (threadIdx.x < NGRAPH) s[threadIdx.x] = 0.0f;
    __syncthreads();
    for (int n = blockIdx.x * blockDim.x + threadIdx.x; n < N;
         n += gridDim.x * blockDim.x)
        atomicAdd(&s[batch[n]], 1.0f);
    __syncthreads();
    if (threadIdx.x < NGRAPH && s[threadIdx.x] > 0.0f)
        atomicAdd(&g_cnt[threadIdx.x], s[threadIdx.x]);
}

__global__ void gdiv_kernel(float* __restrict__ gsum) {
    int i = blockIdx.x * blockDim.x + threadIdx.x;
    if (i < NGRAPH * DOUTC) {
        int g = i / DOUTC;
        gsum[i] = gsum[i] / fmaxf(g_cnt[g], 1.0f);
    }
}

__global__ void logits_kernel(const float* __restrict__ ge, const float* __restrict__ Wc,
                              const float* __restrict__ bc, float* __restrict__ out) {
    int t = threadIdx.x;          // 0..127
    int g = t >> 1, j = t & 1;
    float s = __ldg(&bc[j]);
    #pragma unroll 8
    for (int c = 0; c < DOUTC; ++c)
        s += ge[g * DOUTC + c] * __ldg(&Wc[c * 2 + j]);
    out[t] = s;
}

// ---------------------------------------------------------------------------
// launch
// ---------------------------------------------------------------------------
extern "C" void kernel_launch(void* const* d_in, const int* in_sizes, int n_in,
                              void* d_out, int out_size) {
    const float* x     = (const float*)d_in[0];
    const int*   ei    = (const int*)d_in[1];   // [2, E] int32 (jax x64 disabled)
    const int*   batch = (const int*)d_in[2];
    const float* W_in  = (const float*)d_in[3];
    const float* b_in  = (const float*)d_in[4];
    const float* W_mid = (const float*)d_in[5];
    const float* b_mid = (const float*)d_in[6];
    const float* W_out = (const float*)d_in[7];
    const float* b_out = (const float*)d_in[8];
    const float* W_cls = (const float*)d_in[9];
    const float* b_cls = (const float*)d_in[10];

    const int* src = ei;
    const int* dst = ei + NEDGES;

    float *bufA, *bufB, *disp, *cntp;
    cudaGetSymbolAddress((void**)&bufA, g_bufA);
    cudaGetSymbolAddress((void**)&bufB, g_bufB);
    cudaGetSymbolAddress((void**)&disp, g_dis);
    cudaGetSymbolAddress((void**)&cntp, g_cnt);

    float* node   = (float*)d_out;                      // [N, 128]
    float* gsum   = node + (size_t)NNODES * DOUTC;      // [64, 128]
    float* logit  = gsum + NGRAPH * DOUTC;              // [64, 2]

    const int T = 256;

    // deg = 1 (self loop), += in-degree, then dis = rsqrt(deg)
    fill_kernel<<<64, T>>>((float4*)disp, 1.0f, NNODES / 4);
    deg_kernel<<<(NEDGES + T - 1) / T, T>>>(dst, NEDGES);
    rsqrt_kernel<<<(NNODES + T - 1) / T, T>>>(NNODES);

    // ----- layer 1: x[N,128] @ W_in[128,256] -----
    gemm_kernel<<<dim3(DH / 64, NNODES / 64), dim3(16, 16)>>>(x, W_in, bufA, DIN, DH);
    fill_kernel<<<4096, T>>>((float4*)bufB, 0.0f, NNODES * DH / 4);
    scatter_kernel<DH><<<(NEDGES * 32) / T, T>>>(src, dst, bufA, bufB, NEDGES);
    finalize_kernel<true, DH><<<(NNODES * DH + T - 1) / T, T>>>(bufB, bufA, b_in, NNODES * DH);

    // ----- layer 2: h1[N,256] @ W_mid[256,256] -----
    gemm_kernel<<<dim3(DH / 64, NNODES / 64), dim3(16, 16)>>>(bufB, W_mid, bufA, DH, DH);
    fill_kernel<<<4096, T>>>((float4*)bufB, 0.0f, NNODES * DH / 4);
    scatter_kernel<DH><<<(NEDGES * 32) / T, T>>>(src, dst, bufA, bufB, NEDGES);
    finalize_kernel<true, DH><<<(NNODES * DH + T - 1) / T, T>>>(bufB, bufA, b_mid, NNODES * DH);

    // ----- layer 3: h2[N,256] @ W_out[256,128], agg directly into d_out -----
    gemm_kernel<<<dim3(DOUTC / 64, NNODES / 64), dim3(16, 16)>>>(bufB, W_out, bufA, DH, DOUTC);
    fill_kernel<<<4096, T>>>((float4*)node, 0.0f, NNODES * DOUTC / 4);
    scatter_kernel<DOUTC><<<(NEDGES * 32) / T, T>>>(src, dst, bufA, node, NEDGES);
    finalize_kernel<false, DOUTC><<<(NNODES * DOUTC + T - 1) / T, T>>>(node, bufA, b_out,
                                                                       NNODES * DOUTC);

    // ----- mean pool + classifier -----
    fill_kernel<<<8, T>>>((float4*)gsum, 0.0f, NGRAPH * DOUTC / 4);
    fill_kernel<<<1, 16>>>((float4*)cntp, 0.0f, NGRAPH / 4);
    counts_kernel<<<64, T>>>(batch, NNODES);
    pool_kernel<<<(NNODES + 255) / 256, 128>>>(node, batch, gsum, NNODES);
    gdiv_kernel<<<(NGRAPH * DOUTC + T - 1) / T, T>>>(gsum);
    logits_kernel<<<1, 128>>>(gsum, W_cls, b_cls, logit);
}

// round 2
// speedup vs baseline: 1.3031x; 1.3031x over previous
#include <cuda_runtime.h>
#include <stdint.h>

#define NNODES 40000
#define NEDGES 640000
#define NGRAPH 64
#define DIN    128
#define DH     256
#define DOUTC  128

// ---- scratch (no allocations allowed) ----
__device__ float g_bufA[NNODES * DH];
__device__ float g_bufB[NNODES * DH];
__device__ float g_dis[NNODES];
__device__ float g_cnt[NGRAPH];
// CSR scratch
__device__ int   g_cnti[NNODES];
__device__ int   g_rowptr[NNODES + 1];
__device__ int   g_cursor[NNODES];
__device__ int   g_esrc[NEDGES];
__device__ float g_ecoef[NEDGES];

// ---------------------------------------------------------------------------
// small utility kernels
// ---------------------------------------------------------------------------
__global__ void fill_kernel(float4* __restrict__ p, float v, int n4) {
    int i = blockIdx.x * blockDim.x + threadIdx.x;
    float4 f = make_float4(v, v, v, v);
    for (; i < n4; i += gridDim.x * blockDim.x) p[i] = f;
}

__global__ void zeroi_kernel(int* __restrict__ p, int n) {
    int i = blockIdx.x * blockDim.x + threadIdx.x;
    if (i < n) p[i] = 0;
}

// histogram of in-degree (without self loop)
__global__ void hist_kernel(const int* __restrict__ dst, int E) {
    int e = blockIdx.x * blockDim.x + threadIdx.x;
    if (e < E) atomicAdd(&g_cnti[dst[e]], 1);
}

// dis = rsqrt(indeg + 1)
__global__ void dis_kernel(int n) {
    int i = blockIdx.x * blockDim.x + threadIdx.x;
    if (i < n) g_dis[i] = rsqrtf((float)g_cnti[i] + 1.0f);
}

// single-block exclusive scan of g_cnti -> g_rowptr / g_cursor
__global__ void scan_kernel() {
    __shared__ int part[1024];
    const int t = threadIdx.x;
    const int CH = (NNODES + 1023) / 1024;   // 40
    int base = t * CH;
    int end  = min(base + CH, NNODES);
    int s = 0;
    for (int i = base; i < end; ++i) s += g_cnti[i];
    part[t] = s;
    __syncthreads();
    // Hillis-Steele inclusive scan
    for (int off = 1; off < 1024; off <<= 1) {
        int v = (t >= off) ? part[t - off] : 0;
        __syncthreads();
        if (t >= off) part[t] += v;
        __syncthreads();
    }
    int run = (t == 0) ? 0 : part[t - 1];
    for (int i = base; i < end; ++i) {
        g_rowptr[i] = run;
        g_cursor[i] = run;
        run += g_cnti[i];
    }
    if (t == 0) g_rowptr[NNODES] = NEDGES;
}

// place each edge in its dst row; store src index + norm coefficient
__global__ void csrfill_kernel(const int* __restrict__ src, const int* __restrict__ dst,
                               int E) {
    int e = blockIdx.x * blockDim.x + threadIdx.x;
    if (e >= E) return;
    int s = src[e], d = dst[e];
    int p = atomicAdd(&g_cursor[d], 1);
    g_esrc[p]  = s;
    g_ecoef[p] = g_dis[s] * g_dis[d];
}

// ---------------------------------------------------------------------------
// fp32 tiled GEMM: C[N,M] = A[N,K] @ B[K,M]
// block (16,16), tile 64x64, K-tile 16, 4x4 per thread.
// ---------------------------------------------------------------------------
__global__ void gemm_kernel(const float* __restrict__ A, const float* __restrict__ B,
                            float* __restrict__ C, int K, int M) {
    __shared__ float As[16][64];
    __shared__ float Bs[16][64];
    const int tid = threadIdx.y * 16 + threadIdx.x;
    const int rowBase = blockIdx.y * 64;
    const int colBase = blockIdx.x * 64;

    float acc[4][4] = {};

    for (int k0 = 0; k0 < K; k0 += 16) {
        {   // A tile: 64 rows x 16 k, one float4 per thread, stored transposed
            int r  = tid >> 2;
            int kk = (tid & 3) * 4;
            float4 v = *(const float4*)(A + (size_t)(rowBase + r) * K + k0 + kk);
            As[kk + 0][r] = v.x; As[kk + 1][r] = v.y;
            As[kk + 2][r] = v.z; As[kk + 3][r] = v.w;
        }
        {   // B tile: 16 k x 64 cols
            int kr = tid >> 4;
            int cc = (tid & 15) * 4;
            float4 v = *(const float4*)(B + (size_t)(k0 + kr) * M + colBase + cc);
            Bs[kr][cc + 0] = v.x; Bs[kr][cc + 1] = v.y;
            Bs[kr][cc + 2] = v.z; Bs[kr][cc + 3] = v.w;
        }
        __syncthreads();
        #pragma unroll
        for (int kk = 0; kk < 16; ++kk) {
            float a[4], b[4];
            #pragma unroll
            for (int i = 0; i < 4; ++i) a[i] = As[kk][threadIdx.y * 4 + i];
            #pragma unroll
            for (int j = 0; j < 4; ++j) b[j] = Bs[kk][threadIdx.x * 4 + j];
            #pragma unroll
            for (int i = 0; i < 4; ++i)
                #pragma unroll
                for (int j = 0; j < 4; ++j) acc[i][j] += a[i] * b[j];
        }
        __syncthreads();
    }
    #pragma unroll
    for (int i = 0; i < 4; ++i) {
        int r = rowBase + threadIdx.y * 4 + i;
        float4 o = make_float4(acc[i][0], acc[i][1], acc[i][2], acc[i][3]);
        *(float4*)(C + (size_t)r * M + colBase + threadIdx.x * 4) = o;
    }
}

// ---------------------------------------------------------------------------
// fused gather + self-loop + bias (+relu):
//   out[n] = sum_{e in CSR row n} coef[e] * h[src[e]]  +  dis[n]^2 * h[n] + bias
// One warp per (node, 128-column slice). Registers hold one float4 per lane.
// ---------------------------------------------------------------------------
template <int H, bool RELU>
__global__ void gather_kernel(const float* __restrict__ h, const float* __restrict__ bias,
                              float* __restrict__ out) {
    constexpr int HALVES = H / 128;
    int w = (blockIdx.x * blockDim.x + threadIdx.x) >> 5;
    int n = w / HALVES;
    if (n >= NNODES) return;
    int half = w - n * HALVES;
    int lane = threadIdx.x & 31;
    int col  = half * 128 + lane * 4;

    int p  = g_rowptr[n];
    int p1 = g_rowptr[n + 1];

    float4 acc = make_float4(0.f, 0.f, 0.f, 0.f);
    // unroll by 2 for MLP
    for (; p + 1 < p1; p += 2) {
        int   s0 = g_esrc[p],     s1 = g_esrc[p + 1];
        float c0 = g_ecoef[p],    c1 = g_ecoef[p + 1];
        float4 v0 = __ldg((const float4*)(h + (size_t)s0 * H + col));
        float4 v1 = __ldg((const float4*)(h + (size_t)s1 * H + col));
        acc.x += c0 * v0.x + c1 * v1.x;
        acc.y += c0 * v0.y + c1 * v1.y;
        acc.z += c0 * v0.z + c1 * v1.z;
        acc.w += c0 * v0.w + c1 * v1.w;
    }
    if (p < p1) {
        int s = g_esrc[p]; float c = g_ecoef[p];
        float4 v = __ldg((const float4*)(h + (size_t)s * H + col));
        acc.x += c * v.x; acc.y += c * v.y; acc.z += c * v.z; acc.w += c * v.w;
    }

    float dis = g_dis[n];
    float c2 = dis * dis;
    float4 hv = __ldg((const float4*)(h + (size_t)n * H + col));
    float4 bv = __ldg((const float4*)(bias + col));
    float4 r;
    r.x = acc.x + c2 * hv.x + bv.x;
    r.y = acc.y + c2 * hv.y + bv.y;
    r.z = acc.z + c2 * hv.z + bv.z;
    r.w = acc.w + c2 * hv.w + bv.w;
    if (RELU) {
        r.x = fmaxf(r.x, 0.f); r.y = fmaxf(r.y, 0.f);
        r.z = fmaxf(r.z, 0.f); r.w = fmaxf(r.w, 0.f);
    }
    *(float4*)(out + (size_t)n * H + col) = r;
}

// ---------------------------------------------------------------------------
// pooling: batch is sorted; accumulate in registers until graph id changes.
// ---------------------------------------------------------------------------
__global__ void pool_kernel(const float* __restrict__ ne, const int* __restrict__ batch,
                            float* __restrict__ gsum, int N) {
    int c  = threadIdx.x;  // 0..127
    int n0 = blockIdx.x * 256;
    int n1 = min(n0 + 256, N);
    float acc = 0.0f;
    int cur = -1;
    for (int n = n0; n < n1; ++n) {
        int g = __ldg(&batch[n]);
        if (g != cur) {
            if (cur >= 0) atomicAdd(&gsum[cur * DOUTC + c], acc);
            acc = 0.0f;
            cur = g;
        }
        acc += ne[(size_t)n * DOUTC + c];
    }
    if (cur >= 0) atomicAdd(&gsum[cur * DOUTC + c], acc);
}

__global__ void counts_kernel(const int* __restrict__ batch, int N) {
    __shared__ float s[NGRAPH];
    if (threadIdx.x < NGRAPH) s[threadIdx.x] = 0.0f;
    __syncthreads();
    for (int n = blockIdx.x * blockDim.x + threadIdx.x; n < N;
         n += gridDim.x * blockDim.x)
        atomicAdd(&s[batch[n]], 1.0f);
    __syncthreads();
    if (threadIdx.x < NGRAPH && s[threadIdx.x] > 0.0f)
        atomicAdd(&g_cnt[threadIdx.x], s[threadIdx.x]);
}

__global__ void gdiv_kernel(float* __restrict__ gsum) {
    int i = blockIdx.x * blockDim.x + threadIdx.x;
    if (i < NGRAPH * DOUTC) {
        int g = i / DOUTC;
        gsum[i] = gsum[i] / fmaxf(g_cnt[g], 1.0f);
    }
}

__global__ void logits_kernel(const float* __restrict__ ge, const float* __restrict__ Wc,
                              const float* __restrict__ bc, float* __restrict__ out) {
    int t = threadIdx.x;          // 0..127
    int g = t >> 1, j = t & 1;
    float s = __ldg(&bc[j]);
    #pragma unroll 8
    for (int c = 0; c < DOUTC; ++c)
        s += ge[g * DOUTC + c] * __ldg(&Wc[c * 2 + j]);
    out[t] = s;
}

// ---------------------------------------------------------------------------
// launch
// ---------------------------------------------------------------------------
extern "C" void kernel_launch(void* const* d_in, const int* in_sizes, int n_in,
                              void* d_out, int out_size) {
    const float* x     = (const float*)d_in[0];
    const int*   ei    = (const int*)d_in[1];   // [2, E] int32
    const int*   batch = (const int*)d_in[2];
    const float* W_in  = (const float*)d_in[3];
    const float* b_in  = (const float*)d_in[4];
    const float* W_mid = (const float*)d_in[5];
    const float* b_mid = (const float*)d_in[6];
    const float* W_out = (const float*)d_in[7];
    const float* b_out = (const float*)d_in[8];
    const float* W_cls = (const float*)d_in[9];
    const float* b_cls = (const float*)d_in[10];

    const int* src = ei;
    const int* dst = ei + NEDGES;

    float *bufA, *bufB, *cntp;
    int *cnti;
    cudaGetSymbolAddress((void**)&bufA, g_bufA);
    cudaGetSymbolAddress((void**)&bufB, g_bufB);
    cudaGetSymbolAddress((void**)&cntp, g_cnt);
    cudaGetSymbolAddress((void**)&cnti, g_cnti);

    float* node   = (float*)d_out;                      // [N, 128]
    float* gsum   = node + (size_t)NNODES * DOUTC;      // [64, 128]
    float* logit  = gsum + NGRAPH * DOUTC;              // [64, 2]

    const int T = 256;

    // ----- CSR build + norm coefficients -----
    zeroi_kernel<<<(NNODES + T - 1) / T, T>>>(cnti, NNODES);
    hist_kernel<<<(NEDGES + T - 1) / T, T>>>(dst, NEDGES);
    dis_kernel<<<(NNODES + T - 1) / T, T>>>(NNODES);
    scan_kernel<<<1, 1024>>>();
    csrfill_kernel<<<(NEDGES + T - 1) / T, T>>>(src, dst, NEDGES);

    // ----- layer 1: x[N,128] @ W_in[128,256], fused gather+bias+relu -----
    gemm_kernel<<<dim3(DH / 64, NNODES / 64), dim3(16, 16)>>>(x, W_in, bufA, DIN, DH);
    gather_kernel<DH, true><<<(NNODES * 2 * 32 + T - 1) / T, T>>>(bufA, b_in, bufB);

    // ----- layer 2 -----
    gemm_kernel<<<dim3(DH / 64, NNODES / 64), dim3(16, 16)>>>(bufB, W_mid, bufA, DH, DH);
    gather_kernel<DH, true><<<(NNODES * 2 * 32 + T - 1) / T, T>>>(bufA, b_mid, bufB);

    // ----- layer 3: result lands directly in d_out node region -----
    gemm_kernel<<<dim3(DOUTC / 64, NNODES / 64), dim3(16, 16)>>>(bufB, W_out, bufA, DH, DOUTC);
    gather_kernel<DOUTC, false><<<(NNODES * 1 * 32 + T - 1) / T, T>>>(bufA, b_out, node);

    // ----- mean pool + classifier -----
    fill_kernel<<<8, T>>>((float4*)gsum, 0.0f, NGRAPH * DOUTC / 4);
    fill_kernel<<<1, 16>>>((float4*)cntp, 0.0f, NGRAPH / 4);
    counts_kernel<<<64, T>>>(batch, NNODES);
    pool_kernel<<<(NNODES + 255) / 256, 128>>>(node, batch, gsum, NNODES);
    gdiv_kernel<<<(NGRAPH * DOUTC + T - 1) / T, T>>>(gsum);
    logits_kernel<<<1, 128>>>(gsum, W_cls, b_cls, logit);
}

// round 3
// speedup vs baseline: 1.4829x; 1.1380x over previous
#include <cuda_runtime.h>
#include <stdint.h>

#define NNODES 40000
#define NEDGES 640000
#define NGRAPH 64
#define DIN    128
#define DH     256
#define DOUTC  128

#define SCAN_B 256
#define SCAN_NB ((NNODES + SCAN_B - 1) / SCAN_B)   // 157

// ---- scratch (no allocations allowed) ----
__device__ float g_bufA[NNODES * DH];
__device__ float g_bufB[NNODES * DH];
__device__ float g_dis[NNODES];
__device__ float g_cnt[NGRAPH];
// CSR scratch
__device__ int   g_cnti[NNODES];
__device__ int   g_rowptr[NNODES + 1];
__device__ int   g_cursor[NNODES];
__device__ int   g_esrc[NEDGES];
__device__ float g_ecoef[NEDGES];
__device__ int   g_bsum[SCAN_NB];
__device__ int   g_bpre[SCAN_NB];

// ---------------------------------------------------------------------------
// small utility kernels
// ---------------------------------------------------------------------------
__global__ void fill_kernel(float4* __restrict__ p, float v, int n4) {
    int i = blockIdx.x * blockDim.x + threadIdx.x;
    float4 f = make_float4(v, v, v, v);
    for (; i < n4; i += gridDim.x * blockDim.x) p[i] = f;
}

__global__ void zeroi_kernel(int* __restrict__ p, int n) {
    int i = blockIdx.x * blockDim.x + threadIdx.x;
    if (i < n) p[i] = 0;
}

// histogram of in-degree (without self loop)
__global__ void hist_kernel(const int* __restrict__ dst, int E) {
    int e = blockIdx.x * blockDim.x + threadIdx.x;
    if (e < E) atomicAdd(&g_cnti[dst[e]], 1);
}

// dis = rsqrt(indeg + 1)
__global__ void dis_kernel(int n) {
    int i = blockIdx.x * blockDim.x + threadIdx.x;
    if (i < n) g_dis[i] = rsqrtf((float)g_cnti[i] + 1.0f);
}

// ---------------------------------------------------------------------------
// three-phase scan of g_cnti -> g_rowptr / g_cursor
// ---------------------------------------------------------------------------
__global__ void scan1_kernel() {            // per-block sums
    __shared__ int s[SCAN_B];
    int i = blockIdx.x * SCAN_B + threadIdx.x;
    s[threadIdx.x] = (i < NNODES) ? g_cnti[i] : 0;
    __syncthreads();
    for (int off = SCAN_B / 2; off > 0; off >>= 1) {
        if (threadIdx.x < off) s[threadIdx.x] += s[threadIdx.x + off];
        __syncthreads();
    }
    if (threadIdx.x == 0) g_bsum[blockIdx.x] = s[0];
}

__global__ void scan2_kernel() {            // exclusive scan of block sums (1 block)
    __shared__ int s[SCAN_NB];
    int t = threadIdx.x;
    if (t < SCAN_NB) s[t] = g_bsum[t];
    __syncthreads();
    // Hillis-Steele inclusive over SCAN_NB entries (threads >= SCAN_NB idle)
    for (int off = 1; off < SCAN_NB; off <<= 1) {
        int v = 0;
        if (t < SCAN_NB && t >= off) v = s[t - off];
        __syncthreads();
        if (t < SCAN_NB && t >= off) s[t] += v;
        __syncthreads();
    }
    if (t < SCAN_NB) g_bpre[t] = (t == 0) ? 0 : s[t - 1];
    if (t == 0) g_rowptr[NNODES] = NEDGES;
}

__global__ void scan3_kernel() {            // in-block exclusive scan + offset
    __shared__ int s[SCAN_B];
    int i = blockIdx.x * SCAN_B + threadIdx.x;
    int t = threadIdx.x;
    int v0 = (i < NNODES) ? g_cnti[i] : 0;
    s[t] = v0;
    __syncthreads();
    for (int off = 1; off < SCAN_B; off <<= 1) {
        int v = (t >= off) ? s[t - off] : 0;
        __syncthreads();
        s[t] += v;
        __syncthreads();
    }
    if (i < NNODES) {
        int ex = g_bpre[blockIdx.x] + s[t] - v0;
        g_rowptr[i] = ex;
        g_cursor[i] = ex;
    }
}

// place each edge in its dst row; store src index + norm coefficient
__global__ void csrfill_kernel(const int* __restrict__ src, const int* __restrict__ dst,
                               int E) {
    int e = blockIdx.x * blockDim.x + threadIdx.x;
    if (e >= E) return;
    int s = src[e], d = dst[e];
    int p = atomicAdd(&g_cursor[d], 1);
    g_esrc[p]  = s;
    g_ecoef[p] = g_dis[s] * g_dis[d];
}

// ---------------------------------------------------------------------------
// fp32 tiled GEMM: C[N,M] = A[N,K] @ B[K,M]
// block (16,16)=256 thr, tile 128x64, K-tile 16, 8x4 per thread.
// Handles N not divisible by 128 (clamped loads, predicated stores).
// ---------------------------------------------------------------------------
__global__ void gemm_kernel(const float* __restrict__ A, const float* __restrict__ B,
                            float* __restrict__ C, int N, int K, int M) {
    __shared__ float As[16][128];
    __shared__ float Bs[16][64];
    const int tid = threadIdx.y * 16 + threadIdx.x;
    const int rowBase = blockIdx.y * 128;
    const int colBase = blockIdx.x * 64;

    float acc[8][4] = {};

    for (int k0 = 0; k0 < K; k0 += 16) {
        #pragma unroll
        for (int l = 0; l < 2; ++l) {       // A tile: 128 rows x 16 k, transposed
            int idx = tid + l * 256;        // 0..511 float4 slots
            int r   = idx >> 2;
            int kk  = (idx & 3) * 4;
            int rr  = min(rowBase + r, N - 1);
            float4 v = *(const float4*)(A + (size_t)rr * K + k0 + kk);
            As[kk + 0][r] = v.x; As[kk + 1][r] = v.y;
            As[kk + 2][r] = v.z; As[kk + 3][r] = v.w;
        }
        {   // B tile: 16 k x 64 cols
            int kr = tid >> 4;
            int cc = (tid & 15) * 4;
            float4 v = *(const float4*)(B + (size_t)(k0 + kr) * M + colBase + cc);
            Bs[kr][cc + 0] = v.x; Bs[kr][cc + 1] = v.y;
            Bs[kr][cc + 2] = v.z; Bs[kr][cc + 3] = v.w;
        }
        __syncthreads();
        #pragma unroll
        for (int kk = 0; kk < 16; ++kk) {
            float a[8], b[4];
            #pragma unroll
            for (int i = 0; i < 8; ++i) a[i] = As[kk][threadIdx.y * 8 + i];
            #pragma unroll
            for (int j = 0; j < 4; ++j) b[j] = Bs[kk][threadIdx.x * 4 + j];
            #pragma unroll
            for (int i = 0; i < 8; ++i)
                #pragma unroll
                for (int j = 0; j < 4; ++j) acc[i][j] += a[i] * b[j];
        }
        __syncthreads();
    }
    #pragma unroll
    for (int i = 0; i < 8; ++i) {
        int r = rowBase + threadIdx.y * 8 + i;
        if (r < N) {
            float4 o = make_float4(acc[i][0], acc[i][1], acc[i][2], acc[i][3]);
            *(float4*)(C + (size_t)r * M + colBase + threadIdx.x * 4) = o;
        }
    }
}

// ---------------------------------------------------------------------------
// fused gather + self-loop + bias (+relu)
// ---------------------------------------------------------------------------
template <int H, bool RELU>
__global__ void gather_kernel(const float* __restrict__ h, const float* __restrict__ bias,
                              float* __restrict__ out) {
    constexpr int HALVES = H / 128;
    int w = (blockIdx.x * blockDim.x + threadIdx.x) >> 5;
    int n = w / HALVES;
    if (n >= NNODES) return;
    int half = w - n * HALVES;
    int lane = threadIdx.x & 31;
    int col  = half * 128 + lane * 4;

    int p  = g_rowptr[n];
    int p1 = g_rowptr[n + 1];

    float4 acc = make_float4(0.f, 0.f, 0.f, 0.f);
    for (; p + 1 < p1; p += 2) {
        int   s0 = g_esrc[p],     s1 = g_esrc[p + 1];
        float c0 = g_ecoef[p],    c1 = g_ecoef[p + 1];
        float4 v0 = __ldg((const float4*)(h + (size_t)s0 * H + col));
        float4 v1 = __ldg((const float4*)(h + (size_t)s1 * H + col));
        acc.x += c0 * v0.x + c1 * v1.x;
        acc.y += c0 * v0.y + c1 * v1.y;
        acc.z += c0 * v0.z + c1 * v1.z;
        acc.w += c0 * v0.w + c1 * v1.w;
    }
    if (p < p1) {
        int s = g_esrc[p]; float c = g_ecoef[p];
        float4 v = __ldg((const float4*)(h + (size_t)s * H + col));
        acc.x += c * v.x; acc.y += c * v.y; acc.z += c * v.z; acc.w += c * v.w;
    }

    float dis = g_dis[n];
    float c2 = dis * dis;
    float4 hv = __ldg((const float4*)(h + (size_t)n * H + col));
    float4 bv = __ldg((const float4*)(bias + col));
    float4 r;
    r.x = acc.x + c2 * hv.x + bv.x;
    r.y = acc.y + c2 * hv.y + bv.y;
    r.z = acc.z + c2 * hv.z + bv.z;
    r.w = acc.w + c2 * hv.w + bv.w;
    if (RELU) {
        r.x = fmaxf(r.x, 0.f); r.y = fmaxf(r.y, 0.f);
        r.z = fmaxf(r.z, 0.f); r.w = fmaxf(r.w, 0.f);
    }
    *(float4*)(out + (size_t)n * H + col) = r;
}

// ---------------------------------------------------------------------------
// pooling: batch is sorted; accumulate in registers until graph id changes.
// ---------------------------------------------------------------------------
__global__ void pool_kernel(const float* __restrict__ ne, const int* __restrict__ batch,
                            float* __restrict__ gsum, int N) {
    int c  = threadIdx.x;  // 0..127
    int n0 = blockIdx.x * 256;
    int n1 = min(n0 + 256, N);
    float acc = 0.0f;
    int cur = -1;
    for (int n = n0; n < n1; ++n) {
        int g = __ldg(&batch[n]);
        if (g != cur) {
            if (cur >= 0) atomicAdd(&gsum[cur * DOUTC + c], acc);
            acc = 0.0f;
            cur = g;
        }
        acc += ne[(size_t)n * DOUTC + c];
    }
    if (cur >= 0) atomicAdd(&gsum[cur * DOUTC + c], acc);
}

__global__ void counts_kernel(const int* __restrict__ batch, int N) {
    __shared__ float s[NGRAPH];
    if (threadIdx.x < NGRAPH) s[threadIdx.x] = 0.0f;
    __syncthreads();
    for (int n = blockIdx.x * blockDim.x + threadIdx.x; n < N;
         n += gridDim.x * blockDim.x)
        atomicAdd(&s[batch[n]], 1.0f);
    __syncthreads();
    if (threadIdx.x < NGRAPH && s[threadIdx.x] > 0.0f)
        atomicAdd(&g_cnt[threadIdx.x], s[threadIdx.x]);
}

__global__ void gdiv_kernel(float* __restrict__ gsum) {
    int i = blockIdx.x * blockDim.x + threadIdx.x;
    if (i < NGRAPH * DOUTC) {
        int g = i / DOUTC;
        gsum[i] = gsum[i] / fmaxf(g_cnt[g], 1.0f);
    }
}

__global__ void logits_kernel(const float* __restrict__ ge, const float* __restrict__ Wc,
                              const float* __restrict__ bc, float* __restrict__ out) {
    int t = threadIdx.x;          // 0..127
    int g = t >> 1, j = t & 1;
    float s = __ldg(&bc[j]);
    #pragma unroll 8
    for (int c = 0; c < DOUTC; ++c)
        s += ge[g * DOUTC + c] * __ldg(&Wc[c * 2 + j]);
    out[t] = s;
}

// ---------------------------------------------------------------------------
// launch
// ---------------------------------------------------------------------------
extern "C" void kernel_launch(void* const* d_in, const int* in_sizes, int n_in,
                              void* d_out, int out_size) {
    const float* x     = (const float*)d_in[0];
    const int*   ei    = (const int*)d_in[1];   // [2, E] int32
    const int*   batch = (const int*)d_in[2];
    const float* W_in  = (const float*)d_in[3];
    const float* b_in  = (const float*)d_in[4];
    const float* W_mid = (const float*)d_in[5];
    const float* b_mid = (const float*)d_in[6];
    const float* W_out = (const float*)d_in[7];
    const float* b_out = (const float*)d_in[8];
    const float* W_cls = (const float*)d_in[9];
    const float* b_cls = (const float*)d_in[10];

    const int* src = ei;
    const int* dst = ei + NEDGES;

    float *bufA, *bufB, *cntp;
    int *cnti;
    cudaGetSymbolAddress((void**)&bufA, g_bufA);
    cudaGetSymbolAddress((void**)&bufB, g_bufB);
    cudaGetSymbolAddress((void**)&cntp, g_cnt);
    cudaGetSymbolAddress((void**)&cnti, g_cnti);

    float* node   = (float*)d_out;                      // [N, 128]
    float* gsum   = node + (size_t)NNODES * DOUTC;      // [64, 128]
    float* logit  = gsum + NGRAPH * DOUTC;              // [64, 2]

    const int T = 256;

    // ----- CSR build + norm coefficients -----
    zeroi_kernel<<<(NNODES + T - 1) / T, T>>>(cnti, NNODES);
    hist_kernel<<<(NEDGES + T - 1) / T, T>>>(dst, NEDGES);
    dis_kernel<<<(NNODES + T - 1) / T, T>>>(NNODES);
    scan1_kernel<<<SCAN_NB, SCAN_B>>>();
    scan2_kernel<<<1, SCAN_B>>>();
    scan3_kernel<<<SCAN_NB, SCAN_B>>>();
    csrfill_kernel<<<(NEDGES + T - 1) / T, T>>>(src, dst, NEDGES);

    // ----- layer 1: x[N,128] @ W_in[128,256], fused gather+bias+relu -----
    gemm_kernel<<<dim3(DH / 64, (NNODES + 127) / 128), dim3(16, 16)>>>(x, W_in, bufA,
                                                                       NNODES, DIN, DH);
    gather_kernel<DH, true><<<(NNODES * 2 * 32 + T - 1) / T, T>>>(bufA, b_in, bufB);

    // ----- layer 2 -----
    gemm_kernel<<<dim3(DH / 64, (NNODES + 127) / 128), dim3(16, 16)>>>(bufB, W_mid, bufA,
                                                                       NNODES, DH, DH);
    gather_kernel<DH, true><<<(NNODES * 2 * 32 + T - 1) / T, T>>>(bufA, b_mid, bufB);

    // ----- layer 3: result lands directly in d_out node region -----
    gemm_kernel<<<dim3(DOUTC / 64, (NNODES + 127) / 128), dim3(16, 16)>>>(bufB, W_out, bufA,
                                                                          NNODES, DH, DOUTC);
    gather_kernel<DOUTC, false><<<(NNODES * 1 * 32 + T - 1) / T, T>>>(bufA, b_out, node);

    // ----- mean pool + classifier -----
    fill_kernel<<<8, T>>>((float4*)gsum, 0.0f, NGRAPH * DOUTC / 4);
    fill_kernel<<<1, 16>>>((float4*)cntp, 0.0f, NGRAPH / 4);
    counts_kernel<<<64, T>>>(batch, NNODES);
    pool_kernel<<<(NNODES + 255) / 256, 128>>>(node, batch, gsum, NNODES);
    gdiv_kernel<<<(NGRAPH * DOUTC + T - 1) / T, T>>>(gsum);
    logits_kernel<<<1, 128>>>(gsum, W_cls, b_cls, logit);
}